// round 3
// baseline (speedup 1.0000x reference)
#include <cuda_runtime.h>
#include <cuda_bf16.h>
#include <float.h>
#include <math.h>

// ---------------- problem constants (match reference_code) ----------------
#define BGR   256                 // graphs
#define NND   400                 // nodes per graph
#define DIM   256                 // feature dim
#define DEG   32
#define EDG   (BGR * NND * DEG)   // 3,276,800 edges
#define KSEL  200                 // ceil(0.5*400)
#define NCOM  (NND - KSEL)        // 200
#define NTOT  (BGR * NND)         // 102,400 nodes
#define BK    (BGR * KSEL)        // 51,200
#define BC    (BGR * NCOM)        // 51,200
#define STRIDE 96                 // max in-degree capacity (Poisson(32), 11 sigma)

// output layout: concatenation (float32) of
//  feature_dis [BK,DIM], feature_com [BC,DIM], perm [BK], perm_com [BC],
//  score_soft [NTOT], e_dis_mask [EDG], e_com_mask [EDG]
#define O_FDIS  ((size_t)0)
#define O_FCOM  (O_FDIS + (size_t)BK * DIM)
#define O_PERM  (O_FCOM + (size_t)BC * DIM)
#define O_PCOM  (O_PERM + (size_t)BK)
#define O_SOFT  (O_PCOM + (size_t)BC)
#define O_EDIS  (O_SOFT + (size_t)NTOT)
#define O_ECOM  (O_EDIS + (size_t)EDG)

// ---------------- device-global scratch ----------------
__device__ float          g_h[NTOT];              // (X.W)*norm_out, fp32 (as reference)
__device__ float          g_scoref[NTOT];         // final score, fp32 (as reference)
__device__ int            g_degout[NTOT];
__device__ int            g_degin[NTOT];
__device__ unsigned char  g_sel[NTOT];
__device__ int            g_permi[BK];
__device__ int            g_comi[BC];
__device__ double         g_red[2];               // [0]=max, [1]=sum (softmax)
__device__ int            g_bucket[(size_t)NTOT * STRIDE]; // in-edges per node, EDGE-ID ORDER

// ---------------- kernels -------------------------------------------------

__global__ void k_zero() {
    int i = blockIdx.x * blockDim.x + threadIdx.x;
    if (i < NTOT) g_sel[i] = 0;
}

// One warp per graph. Walks the graph's 12800 edges IN EDGE-ID ORDER, placing
// each edge's src into bucket[dst][slot] where slot is the running count of
// earlier same-dst edges. This reproduces XLA-CPU scatter ordering exactly.
__global__ void k_build(const int* __restrict__ src, const int* __restrict__ dst) {
    __shared__ int cin[NND];
    __shared__ int cout[NND];
    int g    = blockIdx.x;
    int lane = threadIdx.x;   // 0..31
    for (int i = lane; i < NND; i += 32) { cin[i] = 0; cout[i] = 0; }
    __syncwarp();

    int base = g * NND * DEG;
    #pragma unroll 1
    for (int it = 0; it < (NND * DEG) / 32; it++) {
        int e  = base + it * 32 + lane;
        int s  = src[e];
        int d  = dst[e];
        int dl = d - g * NND;
        int sl = s - g * NND;
        unsigned m    = __match_any_sync(0xffffffffu, dl);
        int      lead = __ffs(m) - 1;
        int      rank = __popc(m & ((1u << lane) - 1u));
        int      cbase = cin[dl];                 // value before this iteration's update
        int      slot  = cbase + rank;
        if (slot < STRIDE)
            g_bucket[(size_t)d * STRIDE + slot] = s;
        __syncwarp();
        if (lane == lead) cin[dl] = cbase + __popc(m);
        atomicAdd(&cout[sl], 1);
        __syncwarp();
    }
    for (int i = lane; i < NND; i += 32) {
        g_degin[g * NND + i]  = cin[i];
        g_degout[g * NND + i] = cout[i];
    }
}

// h[v] = fl32( (feature[v].W) ) * norm_out  (warp per node, fp32 FMA partials)
__global__ void k_xw(const float* __restrict__ f, const float* __restrict__ W) {
    int gt   = blockIdx.x * blockDim.x + threadIdx.x;
    int node = gt >> 5;
    int lane = gt & 31;
    if (node >= NTOT) return;
    const float4* fr = reinterpret_cast<const float4*>(f) + (size_t)node * (DIM / 4);
    const float4* w4 = reinterpret_cast<const float4*>(W);
    float s = 0.0f;
    #pragma unroll
    for (int half = 0; half < 2; half++) {
        float4 a = fr[lane + half * 32];
        float4 w = w4[lane + half * 32];
        s = fmaf(a.x, w.x, s);
        s = fmaf(a.y, w.y, s);
        s = fmaf(a.z, w.z, s);
        s = fmaf(a.w, w.w, s);
    }
    #pragma unroll
    for (int o = 16; o; o >>= 1)
        s = __fadd_rn(s, __shfl_down_sync(0xffffffffu, s, o));
    if (lane == 0) {
        float dg = fmaxf((float)g_degout[node], 1.0f);
        float no = __fdiv_rn(1.0f, __fsqrt_rn(dg));
        g_h[node] = __fmul_rn(s, no);
    }
}

// agg[v] = sequential fp32 sum of h[src] over in-edges IN EDGE ORDER,
// then score = fl32(agg*norm_in) + b  (separate roundings, like XLA ops)
__global__ void k_agg(const float* __restrict__ b) {
    int v = blockIdx.x * blockDim.x + threadIdx.x;
    if (v >= NTOT) return;
    int d = g_degin[v];
    int dc = d < STRIDE ? d : STRIDE;
    float s = 0.0f;
    const int* bucket = g_bucket + (size_t)v * STRIDE;
    #pragma unroll 1
    for (int i = 0; i < dc; i++)
        s = __fadd_rn(s, g_h[bucket[i]]);
    float dg = fmaxf((float)d, 1.0f);
    float ni = __fdiv_rn(1.0f, __fsqrt_rn(dg));
    g_scoref[v] = __fadd_rn(__fmul_rn(s, ni), b[0]);
}

// per-graph top-k via bitonic sort of 512 padded (score, idx) pairs.
// fp32-bit comparisons, ties broken by LOWER index (lax.top_k semantics).
__global__ void k_topk(float* __restrict__ out) {
    __shared__ float sc[512];
    __shared__ int   si[512];
    int g   = blockIdx.x;
    int tid = threadIdx.x;

    #pragma unroll
    for (int t = tid; t < 512; t += 256) {
        if (t < NND) { sc[t] = g_scoref[g * NND + t]; si[t] = t; }
        else         { sc[t] = -FLT_MAX;              si[t] = t; }
    }
    __syncthreads();

    for (int k = 2; k <= 512; k <<= 1) {
        for (int j = k >> 1; j > 0; j >>= 1) {
            #pragma unroll
            for (int t = tid; t < 512; t += 256) {
                int ixj = t ^ j;
                if (ixj > t) {
                    float s1 = sc[t], s2 = sc[ixj];
                    int   i1 = si[t], i2 = si[ixj];
                    bool firstBetter = (s1 > s2) || (s1 == s2 && i1 < i2);
                    bool up = ((t & k) == 0);
                    if (up ? !firstBetter : firstBetter) {
                        sc[t] = s2; sc[ixj] = s1;
                        si[t] = i2; si[ixj] = i1;
                    }
                }
            }
            __syncthreads();
        }
    }

    for (int t = tid; t < KSEL; t += 256) {
        int local = si[t];
        int node  = g * NND + local;
        g_permi[g * KSEL + t] = node;
        g_sel[node] = 1;
        out[O_PERM + (size_t)g * KSEL + t] = (float)node;
    }
    __syncthreads();

    for (int t = tid; t < NND; t += 256)
        si[t] = (int)g_sel[g * NND + t];
    __syncthreads();

    for (int t = tid; t < NND; t += 256) {
        if (si[t] == 0) {
            int rank = 0;
            for (int i = 0; i < t; i++) rank += (si[i] == 0);
            int node = g * NND + t;
            g_comi[g * NCOM + rank] = node;
            out[O_PCOM + (size_t)g * NCOM + rank] = (float)node;
        }
    }
}

// single-block softmax reduction: max (order-independent) and sum of exp
__global__ void k_reduce() {
    __shared__ double red[1024];
    int tid = threadIdx.x;
    float m = -FLT_MAX;
    for (int i = tid; i < NTOT; i += 1024) m = fmaxf(m, g_scoref[i]);
    red[tid] = (double)m;
    __syncthreads();
    for (int o = 512; o; o >>= 1) {
        if (tid < o) red[tid] = fmax(red[tid], red[tid + o]);
        __syncthreads();
    }
    double mx = red[0];
    __syncthreads();
    double s = 0.0;
    float mxf = (float)mx;
    for (int i = tid; i < NTOT; i += 1024)
        s += (double)expf(__fsub_rn(g_scoref[i], mxf));
    red[tid] = s;
    __syncthreads();
    for (int o = 512; o; o >>= 1) {
        if (tid < o) red[tid] += red[tid + o];
        __syncthreads();
    }
    if (tid == 0) { g_red[0] = mx; g_red[1] = red[0]; }
}

__global__ void k_soft(float* __restrict__ out) {
    int v = blockIdx.x * blockDim.x + threadIdx.x;
    if (v < NTOT) {
        float mxf  = (float)g_red[0];
        float sumf = (float)g_red[1];
        float ex   = expf(__fsub_rn(g_scoref[v], mxf));
        out[O_SOFT + v] = __fdiv_rn(ex, sumf);
    }
}

// gated gathers: 64 threads per output row (64 float4 = 256 floats)
__global__ void k_gather(const float* __restrict__ f, float* __restrict__ out) {
    long long id  = (long long)blockIdx.x * blockDim.x + threadIdx.x;
    long long row = id >> 6;
    int       u   = (int)(id & 63);
    if (row >= 2LL * BK) return;
    int       node;
    size_t    base;
    long long r;
    if (row < BK) { node = g_permi[row];      base = O_FDIS; r = row; }
    else          { node = g_comi[row - BK];  base = O_FCOM; r = row - BK; }
    float s = tanhf(g_scoref[node]);
    const float4* fr = reinterpret_cast<const float4*>(f) + (size_t)node * (DIM / 4);
    float4 v = fr[u];
    v.x = __fmul_rn(v.x, s); v.y = __fmul_rn(v.y, s);
    v.z = __fmul_rn(v.z, s); v.w = __fmul_rn(v.w, s);
    reinterpret_cast<float4*>(out + base)[(size_t)r * (DIM / 4) + u] = v;
}

__global__ void k_mask(const int* __restrict__ src, const int* __restrict__ dst,
                       float* __restrict__ out) {
    int e = blockIdx.x * blockDim.x + threadIdx.x;
    if (e < EDG) {
        int a = g_sel[src[e]];
        int b = g_sel[dst[e]];
        out[O_EDIS + e] = (a & b)        ? 1.0f : 0.0f;
        out[O_ECOM + e] = ((a | b) == 0) ? 1.0f : 0.0f;
    }
}

// ---------------- launch --------------------------------------------------
extern "C" void kernel_launch(void* const* d_in, const int* in_sizes, int n_in,
                              void* d_out, int out_size) {
    const float* feature = (const float*)d_in[0];
    const float* W       = (const float*)d_in[1];
    const float* b       = (const float*)d_in[2];
    const int*   src     = (const int*)d_in[3];
    const int*   dst     = (const int*)d_in[4];
    float*       out     = (float*)d_out;

    const int T = 256;
    k_zero<<<(NTOT + T - 1) / T, T>>>();
    k_build<<<BGR, 32>>>(src, dst);
    k_xw<<<(NTOT * 32 + T - 1) / T, T>>>(feature, W);
    k_agg<<<(NTOT + T - 1) / T, T>>>(b);
    k_topk<<<BGR, 256>>>(out);
    k_reduce<<<1, 1024>>>();
    k_soft<<<(NTOT + T - 1) / T, T>>>(out);
    {
        long long total = 2LL * BK * 64;
        k_gather<<<(unsigned)((total + T - 1) / T), T>>>(feature, out);
    }
    k_mask<<<(EDG + T - 1) / T, T>>>(src, dst, out);
}

// round 4
// speedup vs baseline: 1.8602x; 1.8602x over previous
#include <cuda_runtime.h>
#include <cuda_bf16.h>
#include <float.h>
#include <math.h>

// ---------------- problem constants ----------------
#define BGR   256
#define NND   400
#define DIM   256
#define DEG   32
#define EDG   (BGR * NND * DEG)   // 3,276,800
#define KSEL  200
#define NCOM  (NND - KSEL)        // 200
#define NTOT  (BGR * NND)         // 102,400
#define BK    (BGR * KSEL)        // 51,200
#define BC    (BGR * NCOM)        // 51,200
#define STRIDE 96                 // max in-degree capacity
#define EPG   (NND * DEG)         // 12,800 edges per graph
#define BWRP  32                  // warps per build block
#define EPW   (EPG / BWRP)        // 400 edges per warp

// output layout (float32 concatenation)
#define O_FDIS  ((size_t)0)
#define O_FCOM  (O_FDIS + (size_t)BK * DIM)
#define O_PERM  (O_FCOM + (size_t)BC * DIM)
#define O_PCOM  (O_PERM + (size_t)BK)
#define O_SOFT  (O_PCOM + (size_t)BC)
#define O_EDIS  (O_SOFT + (size_t)NTOT)
#define O_ECOM  (O_EDIS + (size_t)EDG)

// ---------------- device-global scratch ----------------
__device__ float          g_h[NTOT];
__device__ float          g_scoref[NTOT];
__device__ int            g_degout[NTOT];
__device__ int            g_degin[NTOT];
__device__ unsigned char  g_sel[NTOT];
__device__ int            g_permi[BK];
__device__ int            g_comi[BC];
__device__ double         g_red[2];
__device__ int            g_bucket[(size_t)NTOT * STRIDE]; // in-edges, EDGE-ID ORDER

// ---------------- kernels -------------------------------------------------

// Parallel deterministic bucket build. One block (32 warps) per graph.
// Warp w owns edges [w*EPW, (w+1)*EPW) of its graph, in edge-id order.
// Phase 1: per-warp dst histogram (smem atomics, order-free counts).
// Phase 2: exclusive scan across warps per dst -> per-warp start slot.
// Phase 3: ordered replay with match_any rank => slots identical to a fully
//          sequential edge-order scatter.
__global__ __launch_bounds__(1024) void k_build(const int* __restrict__ src,
                                                const int* __restrict__ dst) {
    __shared__ int cnt[BWRP][NND];   // 51.2 KB
    __shared__ int cout[NND];
    int g    = blockIdx.x;
    int tid  = threadIdx.x;
    int w    = tid >> 5;
    int lane = tid & 31;

    for (int i = tid; i < BWRP * NND; i += 1024) (&cnt[0][0])[i] = 0;
    for (int i = tid; i < NND; i += 1024) cout[i] = 0;
    __syncthreads();

    int gbase = g * EPG;
    int wbase = gbase + w * EPW;

    // Phase 1: counts
    #pragma unroll 1
    for (int it = 0; it < (EPW + 31) / 32; it++) {
        int li = it * 32 + lane;
        if (li < EPW) {
            int e = wbase + li;
            atomicAdd(&cnt[w][dst[e] - g * NND], 1);
            atomicAdd(&cout[src[e] - g * NND], 1);
        }
    }
    __syncthreads();

    // Phase 2: exclusive scan across warps for each dst
    for (int d = tid; d < NND; d += 1024) {
        int run = 0;
        #pragma unroll
        for (int w2 = 0; w2 < BWRP; w2++) {
            int c = cnt[w2][d];
            cnt[w2][d] = run;
            run += c;
        }
        g_degin[g * NND + d]  = run;
        g_degout[g * NND + d] = cout[d];
    }
    __syncthreads();

    // Phase 3: ordered replay
    #pragma unroll 1
    for (int it = 0; it < (EPW + 31) / 32; it++) {
        int li = it * 32 + lane;
        bool act = (li < EPW);
        int s = 0, d = 0, key;
        if (act) {
            int e = wbase + li;
            s = src[e];
            d = dst[e];
            key = d - g * NND;            // 0..399
        } else {
            key = NND + lane;             // unique, never matches a real dst
        }
        unsigned m    = __match_any_sync(0xffffffffu, key);
        int      lead = __ffs(m) - 1;
        int      rank = __popc(m & ((1u << lane) - 1u));
        int cb = 0;
        if (act) cb = cnt[w][key];
        __syncwarp();
        if (act) {
            int slot = cb + rank;
            if (slot < STRIDE)
                g_bucket[(size_t)d * STRIDE + slot] = s;
            if (lane == lead)
                cnt[w][key] = cb + __popc(m);
        }
        __syncwarp();
    }
}

// h[v] = fl32(feature[v].W) * norm_out  (warp per node)
__global__ void k_xw(const float* __restrict__ f, const float* __restrict__ W) {
    int gt   = blockIdx.x * blockDim.x + threadIdx.x;
    int node = gt >> 5;
    int lane = gt & 31;
    if (node >= NTOT) return;
    const float4* fr = reinterpret_cast<const float4*>(f) + (size_t)node * (DIM / 4);
    const float4* w4 = reinterpret_cast<const float4*>(W);
    float s = 0.0f;
    #pragma unroll
    for (int half = 0; half < 2; half++) {
        float4 a = fr[lane + half * 32];
        float4 w = w4[lane + half * 32];
        s = fmaf(a.x, w.x, s);
        s = fmaf(a.y, w.y, s);
        s = fmaf(a.z, w.z, s);
        s = fmaf(a.w, w.w, s);
    }
    #pragma unroll
    for (int o = 16; o; o >>= 1)
        s = __fadd_rn(s, __shfl_down_sync(0xffffffffu, s, o));
    if (lane == 0) {
        float dg = fmaxf((float)g_degout[node], 1.0f);
        float no = __fdiv_rn(1.0f, __fsqrt_rn(dg));
        g_h[node] = __fmul_rn(s, no);
    }
}

// agg[v] = sequential fp32 sum over in-edges IN EDGE ORDER (loads batched x8),
// score = fl32(agg*norm_in) + b
__global__ void k_agg(const float* __restrict__ b) {
    int v = blockIdx.x * blockDim.x + threadIdx.x;
    if (v >= NTOT) return;
    int d  = g_degin[v];
    int dc = d < STRIDE ? d : STRIDE;
    const int* bk = g_bucket + (size_t)v * STRIDE;
    float s = 0.0f;
    int i = 0;
    #pragma unroll 1
    for (; i + 8 <= dc; i += 8) {
        int4 a  = *reinterpret_cast<const int4*>(bk + i);
        int4 b2 = *reinterpret_cast<const int4*>(bk + i + 4);
        float h0 = g_h[a.x],  h1 = g_h[a.y],  h2 = g_h[a.z],  h3 = g_h[a.w];
        float h4 = g_h[b2.x], h5 = g_h[b2.y], h6 = g_h[b2.z], h7 = g_h[b2.w];
        s = __fadd_rn(s, h0); s = __fadd_rn(s, h1);
        s = __fadd_rn(s, h2); s = __fadd_rn(s, h3);
        s = __fadd_rn(s, h4); s = __fadd_rn(s, h5);
        s = __fadd_rn(s, h6); s = __fadd_rn(s, h7);
    }
    #pragma unroll 1
    for (; i < dc; i++)
        s = __fadd_rn(s, g_h[bk[i]]);
    float dg = fmaxf((float)d, 1.0f);
    float ni = __fdiv_rn(1.0f, __fsqrt_rn(dg));
    g_scoref[v] = __fadd_rn(__fmul_rn(s, ni), b[0]);
}

// per-graph top-k: bitonic sort of 512 (score,idx), fp32 compare, low-idx ties.
// Also writes full g_sel (0/1) and complement via parallel scan.
__global__ void k_topk(float* __restrict__ out) {
    __shared__ float sc[512];
    __shared__ int   si[512];
    __shared__ int   flag[512];
    __shared__ int   pA[512];
    __shared__ int   pB[512];
    int g   = blockIdx.x;
    int tid = threadIdx.x;

    #pragma unroll
    for (int t = tid; t < 512; t += 256) {
        if (t < NND) { sc[t] = g_scoref[g * NND + t]; si[t] = t; }
        else         { sc[t] = -FLT_MAX;              si[t] = t; }
    }
    __syncthreads();

    for (int k = 2; k <= 512; k <<= 1) {
        for (int j = k >> 1; j > 0; j >>= 1) {
            #pragma unroll
            for (int t = tid; t < 512; t += 256) {
                int ixj = t ^ j;
                if (ixj > t) {
                    float s1 = sc[t], s2 = sc[ixj];
                    int   i1 = si[t], i2 = si[ixj];
                    bool firstBetter = (s1 > s2) || (s1 == s2 && i1 < i2);
                    bool up = ((t & k) == 0);
                    if (up ? !firstBetter : firstBetter) {
                        sc[t] = s2; sc[ixj] = s1;
                        si[t] = i2; si[ixj] = i1;
                    }
                }
            }
            __syncthreads();
        }
    }

    #pragma unroll
    for (int t = tid; t < 512; t += 256) flag[t] = 0;
    __syncthreads();

    for (int t = tid; t < KSEL; t += 256) {
        int local = si[t];
        flag[local] = 1;
        int node = g * NND + local;
        g_permi[g * KSEL + t] = node;
        g_sel[node] = 1;
        out[O_PERM + (size_t)g * KSEL + t] = (float)node;
    }
    __syncthreads();

    // zero sel for unselected + init scan input
    #pragma unroll
    for (int t = tid; t < 512; t += 256) {
        int nf = (t < NND) ? (1 - flag[t]) : 0;
        pA[t] = nf;
        if (t < NND && nf) g_sel[g * NND + t] = 0;
    }
    __syncthreads();

    // inclusive Hillis-Steele scan over 512 (ping-pong)
    int* cur = pA;
    int* nxt = pB;
    for (int off = 1; off < 512; off <<= 1) {
        #pragma unroll
        for (int t = tid; t < 512; t += 256)
            nxt[t] = cur[t] + (t >= off ? cur[t - off] : 0);
        __syncthreads();
        int* tmp = cur; cur = nxt; nxt = tmp;
    }

    for (int t = tid; t < NND; t += 256) {
        if (!flag[t]) {
            int rank = cur[t] - 1;
            int node = g * NND + t;
            g_comi[g * NCOM + rank] = node;
            out[O_PCOM + (size_t)g * NCOM + rank] = (float)node;
        }
    }
}

// single-block softmax reduction (max, then sum of exp in double)
__global__ void k_reduce() {
    __shared__ double red[1024];
    int tid = threadIdx.x;
    float m0 = -FLT_MAX, m1 = -FLT_MAX, m2 = -FLT_MAX, m3 = -FLT_MAX;
    #pragma unroll 1
    for (int base = tid; base < NTOT; base += 4096) {
        m0 = fmaxf(m0, g_scoref[base]);
        m1 = fmaxf(m1, g_scoref[base + 1024]);
        m2 = fmaxf(m2, g_scoref[base + 2048]);
        m3 = fmaxf(m3, g_scoref[base + 3072]);
    }
    float m = fmaxf(fmaxf(m0, m1), fmaxf(m2, m3));
    red[tid] = (double)m;
    __syncthreads();
    for (int o = 512; o; o >>= 1) {
        if (tid < o) red[tid] = fmax(red[tid], red[tid + o]);
        __syncthreads();
    }
    double mx = red[0];
    float mxf = (float)mx;
    __syncthreads();
    double s0 = 0.0, s1 = 0.0, s2 = 0.0, s3 = 0.0;
    #pragma unroll 1
    for (int base = tid; base < NTOT; base += 4096) {
        s0 += (double)expf(__fsub_rn(g_scoref[base],        mxf));
        s1 += (double)expf(__fsub_rn(g_scoref[base + 1024], mxf));
        s2 += (double)expf(__fsub_rn(g_scoref[base + 2048], mxf));
        s3 += (double)expf(__fsub_rn(g_scoref[base + 3072], mxf));
    }
    red[tid] = (s0 + s1) + (s2 + s3);
    __syncthreads();
    for (int o = 512; o; o >>= 1) {
        if (tid < o) red[tid] += red[tid + o];
        __syncthreads();
    }
    if (tid == 0) { g_red[0] = mx; g_red[1] = red[0]; }
}

__global__ void k_soft(float* __restrict__ out) {
    int v = blockIdx.x * blockDim.x + threadIdx.x;
    if (v < NTOT) {
        float mxf  = (float)g_red[0];
        float sumf = (float)g_red[1];
        float ex   = expf(__fsub_rn(g_scoref[v], mxf));
        out[O_SOFT + v] = __fdiv_rn(ex, sumf);
    }
}

// gated gathers: 64 threads per output row
__global__ void k_gather(const float* __restrict__ f, float* __restrict__ out) {
    long long id  = (long long)blockIdx.x * blockDim.x + threadIdx.x;
    long long row = id >> 6;
    int       u   = (int)(id & 63);
    if (row >= 2LL * BK) return;
    int       node;
    size_t    base;
    long long r;
    if (row < BK) { node = g_permi[row];     base = O_FDIS; r = row; }
    else          { node = g_comi[row - BK]; base = O_FCOM; r = row - BK; }
    float s = tanhf(g_scoref[node]);
    const float4* fr = reinterpret_cast<const float4*>(f) + (size_t)node * (DIM / 4);
    float4 v = fr[u];
    v.x = __fmul_rn(v.x, s); v.y = __fmul_rn(v.y, s);
    v.z = __fmul_rn(v.z, s); v.w = __fmul_rn(v.w, s);
    reinterpret_cast<float4*>(out + base)[(size_t)r * (DIM / 4) + u] = v;
}

__global__ void k_mask(const int* __restrict__ src, const int* __restrict__ dst,
                       float* __restrict__ out) {
    int e = blockIdx.x * blockDim.x + threadIdx.x;
    if (e < EDG) {
        int a = g_sel[src[e]];
        int b = g_sel[dst[e]];
        out[O_EDIS + e] = (a & b)        ? 1.0f : 0.0f;
        out[O_ECOM + e] = ((a | b) == 0) ? 1.0f : 0.0f;
    }
}

// ---------------- launch --------------------------------------------------
extern "C" void kernel_launch(void* const* d_in, const int* in_sizes, int n_in,
                              void* d_out, int out_size) {
    const float* feature = (const float*)d_in[0];
    const float* W       = (const float*)d_in[1];
    const float* b       = (const float*)d_in[2];
    const int*   src     = (const int*)d_in[3];
    const int*   dst     = (const int*)d_in[4];
    float*       out     = (float*)d_out;

    const int T = 256;
    k_build<<<BGR, 1024>>>(src, dst);
    k_xw<<<(NTOT * 32 + T - 1) / T, T>>>(feature, W);
    k_agg<<<(NTOT + T - 1) / T, T>>>(b);
    k_topk<<<BGR, 256>>>(out);
    k_reduce<<<1, 1024>>>();
    k_soft<<<(NTOT + T - 1) / T, T>>>(out);
    {
        long long total = 2LL * BK * 64;
        k_gather<<<(unsigned)((total + T - 1) / T), T>>>(feature, out);
    }
    k_mask<<<(EDG + T - 1) / T, T>>>(src, dst, out);
}

// round 7
// speedup vs baseline: 3.0758x; 1.6535x over previous
#include <cuda_runtime.h>
#include <cuda_bf16.h>
#include <float.h>
#include <math.h>

// ---------------- problem constants ----------------
#define BGR   256
#define NND   400
#define DIM   256
#define DEG   32
#define EDG   (BGR * NND * DEG)   // 3,276,800
#define KSEL  200
#define NCOM  (NND - KSEL)        // 200
#define NTOT  (BGR * NND)         // 102,400
#define BK    (BGR * KSEL)        // 51,200
#define BC    (BGR * NCOM)        // 51,200
#define STRIDE 96
#define EPG   (NND * DEG)         // 12,800 edges/graph
#define BWRP  32
#define EPW   (EPG / BWRP)        // 400 edges/warp

// fused kernel A grid split
#define XW_BLOCKS  (NTOT / 32)    // 3200 (32 nodes per 1024-thread block)
#define A_GRID     (BGR + XW_BLOCKS)

// epilogue grid split (256 threads/block)
#define EP_GATHER  ((2 * BK * 64) / 256)   // 25600
#define EP_MASK    (EDG / 256)             // 12800
#define EP_SOFT    (NTOT / 256)            // 400
#define EP_GRID    (EP_GATHER + EP_MASK + EP_SOFT)

// output layout (float32 concatenation)
#define O_FDIS  ((size_t)0)
#define O_FCOM  (O_FDIS + (size_t)BK * DIM)
#define O_PERM  (O_FCOM + (size_t)BC * DIM)
#define O_PCOM  (O_PERM + (size_t)BK)
#define O_SOFT  (O_PCOM + (size_t)BC)
#define O_EDIS  (O_SOFT + (size_t)NTOT)
#define O_ECOM  (O_EDIS + (size_t)EDG)

// ---------------- device-global scratch ----------------
__device__ float          g_dot[NTOT];    // raw feature.W
__device__ float          g_h[NTOT];      // dot * norm_out
__device__ float          g_scoref[NTOT];
__device__ int            g_degout[NTOT];
__device__ int            g_degin[NTOT];
__device__ unsigned char  g_sel[NTOT];
__device__ int            g_permi[BK];
__device__ int            g_comi[BC];
__device__ double         g_sum[1];       // softmax denominator (sum of exp)
__device__ int            g_bucket[(size_t)NTOT * STRIDE]; // in-edges, EDGE-ID ORDER

// ---------------- fused kernel A: bucket build (blocks<BGR) + X.W dot ------
__global__ __launch_bounds__(1024) void kA(const int* __restrict__ src,
                                           const int* __restrict__ dst,
                                           const float* __restrict__ f,
                                           const float* __restrict__ W) {
    int tid  = threadIdx.x;
    int w    = tid >> 5;
    int lane = tid & 31;

    if (blockIdx.x >= BGR) {
        // ---- X.W raw dot: warp per node ----
        int node = (blockIdx.x - BGR) * 32 + w;
        const float4* fr = reinterpret_cast<const float4*>(f) + (size_t)node * (DIM / 4);
        const float4* w4 = reinterpret_cast<const float4*>(W);
        float s = 0.0f;
        #pragma unroll
        for (int half = 0; half < 2; half++) {
            float4 a = fr[lane + half * 32];
            float4 wv = w4[lane + half * 32];
            s = fmaf(a.x, wv.x, s);
            s = fmaf(a.y, wv.y, s);
            s = fmaf(a.z, wv.z, s);
            s = fmaf(a.w, wv.w, s);
        }
        #pragma unroll
        for (int o = 16; o; o >>= 1)
            s = __fadd_rn(s, __shfl_down_sync(0xffffffffu, s, o));
        if (lane == 0) g_dot[node] = s;
        return;
    }

    // ---- deterministic bucket build: one block per graph ----
    __shared__ int cnt[BWRP][NND];   // 51.2 KB
    __shared__ int cout[NND];
    int g = blockIdx.x;
    if (g == 0 && tid == 0) g_sum[0] = 0.0;

    for (int i = tid; i < BWRP * NND; i += 1024) (&cnt[0][0])[i] = 0;
    for (int i = tid; i < NND; i += 1024) cout[i] = 0;
    __syncthreads();

    int wbase = g * EPG + w * EPW;

    // Phase 1: counts (order-free)
    #pragma unroll 1
    for (int it = 0; it < (EPW + 31) / 32; it++) {
        int li = it * 32 + lane;
        if (li < EPW) {
            int e = wbase + li;
            atomicAdd(&cnt[w][dst[e] - g * NND], 1);
            atomicAdd(&cout[src[e] - g * NND], 1);
        }
    }
    __syncthreads();

    // Phase 2: exclusive scan across warps per dst
    for (int d = tid; d < NND; d += 1024) {
        int run = 0;
        #pragma unroll
        for (int w2 = 0; w2 < BWRP; w2++) {
            int c = cnt[w2][d];
            cnt[w2][d] = run;
            run += c;
        }
        g_degin[g * NND + d]  = run;
        g_degout[g * NND + d] = cout[d];
    }
    __syncthreads();

    // Phase 3: ordered replay (slots == sequential edge-order scatter)
    #pragma unroll 1
    for (int it = 0; it < (EPW + 31) / 32; it++) {
        int li = it * 32 + lane;
        bool act = (li < EPW);
        int s = 0, d = 0, key;
        if (act) {
            int e = wbase + li;
            s = src[e];
            d = dst[e];
            key = d - g * NND;
        } else {
            key = NND + lane;
        }
        unsigned m    = __match_any_sync(0xffffffffu, key);
        int      lead = __ffs(m) - 1;
        int      rank = __popc(m & ((1u << lane) - 1u));
        int cb = 0;
        if (act) cb = cnt[w][key];
        __syncwarp();
        if (act) {
            int slot = cb + rank;
            if (slot < STRIDE)
                g_bucket[(size_t)d * STRIDE + slot] = s;
            if (lane == lead)
                cnt[w][key] = cb + __popc(m);
        }
        __syncwarp();
    }
}

// h[v] = dot[v] * norm_out[v]  (same rounding sequence as before)
__global__ void k_norm() {
    int v = blockIdx.x * blockDim.x + threadIdx.x;
    if (v < NTOT) {
        float dg = fmaxf((float)g_degout[v], 1.0f);
        float no = __fdiv_rn(1.0f, __fsqrt_rn(dg));
        g_h[v] = __fmul_rn(g_dot[v], no);
    }
}

// agg[v] = sequential fp32 sum over in-edges IN EDGE ORDER; score = agg*ni + b
__global__ void k_agg(const float* __restrict__ b) {
    int v = blockIdx.x * blockDim.x + threadIdx.x;
    if (v >= NTOT) return;
    int d  = g_degin[v];
    int dc = d < STRIDE ? d : STRIDE;
    const int* bk = g_bucket + (size_t)v * STRIDE;
    float s = 0.0f;
    int i = 0;
    #pragma unroll 1
    for (; i + 8 <= dc; i += 8) {
        int4 a  = *reinterpret_cast<const int4*>(bk + i);
        int4 b2 = *reinterpret_cast<const int4*>(bk + i + 4);
        float h0 = g_h[a.x],  h1 = g_h[a.y],  h2 = g_h[a.z],  h3 = g_h[a.w];
        float h4 = g_h[b2.x], h5 = g_h[b2.y], h6 = g_h[b2.z], h7 = g_h[b2.w];
        s = __fadd_rn(s, h0); s = __fadd_rn(s, h1);
        s = __fadd_rn(s, h2); s = __fadd_rn(s, h3);
        s = __fadd_rn(s, h4); s = __fadd_rn(s, h5);
        s = __fadd_rn(s, h6); s = __fadd_rn(s, h7);
    }
    #pragma unroll 1
    for (; i < dc; i++)
        s = __fadd_rn(s, g_h[bk[i]]);
    float dg = fmaxf((float)d, 1.0f);
    float ni = __fdiv_rn(1.0f, __fsqrt_rn(dg));
    g_scoref[v] = __fadd_rn(__fmul_rn(s, ni), b[0]);
}

// per-graph top-k (bitonic, fp32 cmp, low-idx ties) + sel/complement + exp-sum
__global__ void k_topk(float* __restrict__ out) {
    __shared__ float sc[512];
    __shared__ int   si[512];
    __shared__ int   flag[512];
    __shared__ int   pA[512];
    __shared__ int   pB[512];
    __shared__ double dred[256];
    int g   = blockIdx.x;
    int tid = threadIdx.x;

    #pragma unroll
    for (int t = tid; t < 512; t += 256) {
        if (t < NND) { sc[t] = g_scoref[g * NND + t]; si[t] = t; }
        else         { sc[t] = -FLT_MAX;              si[t] = t; }
    }
    __syncthreads();

    // softmax partial: sum of exp over this graph's 400 scores (padding -> 0)
    {
        double s = 0.0;
        #pragma unroll
        for (int t = tid; t < 512; t += 256)
            s += (double)expf(sc[t]);
        dred[tid] = s;
    }

    for (int k = 2; k <= 512; k <<= 1) {
        for (int j = k >> 1; j > 0; j >>= 1) {
            #pragma unroll
            for (int t = tid; t < 512; t += 256) {
                int ixj = t ^ j;
                if (ixj > t) {
                    float s1 = sc[t], s2 = sc[ixj];
                    int   i1 = si[t], i2 = si[ixj];
                    bool firstBetter = (s1 > s2) || (s1 == s2 && i1 < i2);
                    bool up = ((t & k) == 0);
                    if (up ? !firstBetter : firstBetter) {
                        sc[t] = s2; sc[ixj] = s1;
                        si[t] = i2; si[ixj] = i1;
                    }
                }
            }
            __syncthreads();
        }
    }

    #pragma unroll
    for (int t = tid; t < 512; t += 256) flag[t] = 0;
    __syncthreads();

    for (int t = tid; t < KSEL; t += 256) {
        int local = si[t];
        flag[local] = 1;
        int node = g * NND + local;
        g_permi[g * KSEL + t] = node;
        g_sel[node] = 1;
        out[O_PERM + (size_t)g * KSEL + t] = (float)node;
    }
    __syncthreads();

    #pragma unroll
    for (int t = tid; t < 512; t += 256) {
        int nf = (t < NND) ? (1 - flag[t]) : 0;
        pA[t] = nf;
        if (t < NND && nf) g_sel[g * NND + t] = 0;
    }
    __syncthreads();

    int* cur = pA;
    int* nxt = pB;
    for (int off = 1; off < 512; off <<= 1) {
        #pragma unroll
        for (int t = tid; t < 512; t += 256)
            nxt[t] = cur[t] + (t >= off ? cur[t - off] : 0);
        __syncthreads();
        int* tmp = cur; cur = nxt; nxt = tmp;
    }

    for (int t = tid; t < NND; t += 256) {
        if (!flag[t]) {
            int rank = cur[t] - 1;
            int node = g * NND + t;
            g_comi[g * NCOM + rank] = node;
            out[O_PCOM + (size_t)g * NCOM + rank] = (float)node;
        }
    }

    // finish exp-sum reduction
    __syncthreads();
    for (int o = 128; o; o >>= 1) {
        if (tid < o) dred[tid] += dred[tid + o];
        __syncthreads();
    }
    if (tid == 0) atomicAdd(g_sum, dred[0]);
}

// fused epilogue: gather (blocks [0,25600)), mask [25600,38400), soft [38400,38800)
__global__ __launch_bounds__(256) void k_epi(const float* __restrict__ f,
                                             const int* __restrict__ src,
                                             const int* __restrict__ dst,
                                             float* __restrict__ out) {
    int b   = blockIdx.x;
    int tid = threadIdx.x;

    if (b < EP_GATHER) {
        long long id  = (long long)b * 256 + tid;
        long long row = id >> 6;
        int       u   = (int)(id & 63);
        int       node;
        size_t    base;
        long long r;
        if (row < BK) { node = g_permi[row];     base = O_FDIS; r = row; }
        else          { node = g_comi[row - BK]; base = O_FCOM; r = row - BK; }
        float s = tanhf(g_scoref[node]);
        const float4* fr = reinterpret_cast<const float4*>(f) + (size_t)node * (DIM / 4);
        float4 v = fr[u];
        v.x = __fmul_rn(v.x, s); v.y = __fmul_rn(v.y, s);
        v.z = __fmul_rn(v.z, s); v.w = __fmul_rn(v.w, s);
        reinterpret_cast<float4*>(out + base)[(size_t)r * (DIM / 4) + u] = v;
    } else if (b < EP_GATHER + EP_MASK) {
        int e = (b - EP_GATHER) * 256 + tid;
        int a  = g_sel[src[e]];
        int b2 = g_sel[dst[e]];
        out[O_EDIS + e] = (a & b2)        ? 1.0f : 0.0f;
        out[O_ECOM + e] = ((a | b2) == 0) ? 1.0f : 0.0f;
    } else {
        int v = (b - EP_GATHER - EP_MASK) * 256 + tid;
        float sumf = (float)g_sum[0];
        float ex   = expf(g_scoref[v]);
        out[O_SOFT + v] = __fdiv_rn(ex, sumf);
    }
}

// ---------------- launch --------------------------------------------------
extern "C" void kernel_launch(void* const* d_in, const int* in_sizes, int n_in,
                              void* d_out, int out_size) {
    const float* feature = (const float*)d_in[0];
    const float* W       = (const float*)d_in[1];
    const float* b       = (const float*)d_in[2];
    const int*   src     = (const int*)d_in[3];
    const int*   dst     = (const int*)d_in[4];
    float*       out     = (float*)d_out;

    const int T = 256;
    kA<<<A_GRID, 1024>>>(src, dst, feature, W);
    k_norm<<<(NTOT + T - 1) / T, T>>>();
    k_agg<<<(NTOT + T - 1) / T, T>>>(b);
    k_topk<<<BGR, 256>>>(out);
    k_epi<<<EP_GRID, 256>>>(feature, src, dst, out);
}

// round 13
// speedup vs baseline: 3.0766x; 1.0002x over previous
#include <cuda_runtime.h>
#include <cuda_bf16.h>
#include <float.h>
#include <math.h>

// ---------------- problem constants ----------------
#define BGR   256
#define NND   400
#define DIM   256
#define DEG   32
#define EDG   (BGR * NND * DEG)   // 3,276,800
#define KSEL  200
#define NCOM  (NND - KSEL)        // 200
#define NTOT  (BGR * NND)         // 102,400
#define BK    (BGR * KSEL)        // 51,200
#define BC    (BGR * NCOM)        // 51,200
#define STRIDE 96
#define EPG   (NND * DEG)         // 12,800 edges/graph
#define BWRP  32
#define EPW   (EPG / BWRP)        // 400 edges/warp

// fused kernel A grid split
#define XW_BLOCKS  (NTOT / 32)    // 3200
#define A_GRID     (BGR + XW_BLOCKS)

// epilogue grid split (256 threads/block)
#define EP_GATHER  ((2 * BK * 64) / 256)   // 25600
#define EP_MASK    (EDG / 256)             // 12800
#define EP_SOFT    (NTOT / 256)            // 400
#define EP_GRID    (EP_GATHER + EP_MASK + EP_SOFT)

// output layout (float32 concatenation)
#define O_FDIS  ((size_t)0)
#define O_FCOM  (O_FDIS + (size_t)BK * DIM)
#define O_PERM  (O_FCOM + (size_t)BC * DIM)
#define O_PCOM  (O_PERM + (size_t)BK)
#define O_SOFT  (O_PCOM + (size_t)BC)
#define O_EDIS  (O_SOFT + (size_t)NTOT)
#define O_ECOM  (O_EDIS + (size_t)EDG)

// ---------------- device-global scratch ----------------
__device__ float          g_dot[NTOT];    // raw feature.W
__device__ float          g_scoref[NTOT];
__device__ int            g_degout[NTOT];
__device__ int            g_degin[NTOT];
__device__ unsigned char  g_sel[NTOT];
__device__ int            g_permi[BK];
__device__ int            g_comi[BC];
__device__ double         g_sum[1];       // softmax denominator
__device__ int            g_bucket[(size_t)NTOT * STRIDE]; // in-edges, EDGE-ID ORDER

// ---------------- fused kernel A: bucket build (blocks<BGR) + X.W dot ------
__global__ __launch_bounds__(1024) void kA(const int* __restrict__ src,
                                           const int* __restrict__ dst,
                                           const float* __restrict__ f,
                                           const float* __restrict__ W) {
    int tid  = threadIdx.x;
    int w    = tid >> 5;
    int lane = tid & 31;

    if (blockIdx.x >= BGR) {
        // ---- X.W raw dot: warp per node ----
        int node = (blockIdx.x - BGR) * 32 + w;
        const float4* fr = reinterpret_cast<const float4*>(f) + (size_t)node * (DIM / 4);
        const float4* w4 = reinterpret_cast<const float4*>(W);
        float s = 0.0f;
        #pragma unroll
        for (int half = 0; half < 2; half++) {
            float4 a = fr[lane + half * 32];
            float4 wv = w4[lane + half * 32];
            s = fmaf(a.x, wv.x, s);
            s = fmaf(a.y, wv.y, s);
            s = fmaf(a.z, wv.z, s);
            s = fmaf(a.w, wv.w, s);
        }
        #pragma unroll
        for (int o = 16; o; o >>= 1)
            s = __fadd_rn(s, __shfl_down_sync(0xffffffffu, s, o));
        if (lane == 0) g_dot[node] = s;
        return;
    }

    // ---- deterministic bucket build: one block per graph ----
    __shared__ int cnt[BWRP][NND];   // 51.2 KB
    __shared__ int cout[NND];
    int g = blockIdx.x;
    if (g == 0 && tid == 0) g_sum[0] = 0.0;

    for (int i = tid; i < BWRP * NND; i += 1024) (&cnt[0][0])[i] = 0;
    for (int i = tid; i < NND; i += 1024) cout[i] = 0;
    __syncthreads();

    int wbase = g * EPG + w * EPW;

    // Phase 1: counts (order-free)
    #pragma unroll 1
    for (int it = 0; it < (EPW + 31) / 32; it++) {
        int li = it * 32 + lane;
        if (li < EPW) {
            int e = wbase + li;
            atomicAdd(&cnt[w][dst[e] - g * NND], 1);
            atomicAdd(&cout[src[e] - g * NND], 1);
        }
    }
    __syncthreads();

    // Phase 2: exclusive scan across warps per dst
    for (int d = tid; d < NND; d += 1024) {
        int run = 0;
        #pragma unroll
        for (int w2 = 0; w2 < BWRP; w2++) {
            int c = cnt[w2][d];
            cnt[w2][d] = run;
            run += c;
        }
        g_degin[g * NND + d]  = run;
        g_degout[g * NND + d] = cout[d];
    }
    __syncthreads();

    // Phase 3: ordered replay (slots == sequential edge-order scatter)
    #pragma unroll 1
    for (int it = 0; it < (EPW + 31) / 32; it++) {
        int li = it * 32 + lane;
        bool act = (li < EPW);
        int s = 0, d = 0, key;
        if (act) {
            int e = wbase + li;
            s = src[e];
            d = dst[e];
            key = d - g * NND;
        } else {
            key = NND + lane;
        }
        unsigned m    = __match_any_sync(0xffffffffu, key);
        int      lead = __ffs(m) - 1;
        int      rank = __popc(m & ((1u << lane) - 1u));
        int cb = 0;
        if (act) cb = cnt[w][key];
        __syncwarp();
        if (act) {
            int slot = cb + rank;
            if (slot < STRIDE)
                g_bucket[(size_t)d * STRIDE + slot] = s;
            if (lane == lead)
                cnt[w][key] = cb + __popc(m);
        }
        __syncwarp();
    }
}

// per-edge h (identical rounding sequence per node => bit-identical to a
// precomputed h array)
__device__ __forceinline__ float hval(int s) {
    float dg = fmaxf((float)g_degout[s], 1.0f);
    float no = __fdiv_rn(1.0f, __fsqrt_rn(dg));
    return __fmul_rn(g_dot[s], no);
}

// agg[v] = sequential fp32 sum over in-edges IN EDGE ORDER; score = agg*ni + b.
// Also accumulates the softmax denominator (fp64, one atomic per block).
__global__ __launch_bounds__(256) void k_agg(const float* __restrict__ b) {
    __shared__ double dred[256];
    int tid = threadIdx.x;
    int v = blockIdx.x * 256 + tid;

    int d  = g_degin[v];
    int dc = d < STRIDE ? d : STRIDE;
    const int* bk = g_bucket + (size_t)v * STRIDE;
    float s = 0.0f;
    int i = 0;
    #pragma unroll 1
    for (; i + 8 <= dc; i += 8) {
        int4 a  = *reinterpret_cast<const int4*>(bk + i);
        int4 b2 = *reinterpret_cast<const int4*>(bk + i + 4);
        float h0 = hval(a.x),  h1 = hval(a.y),  h2 = hval(a.z),  h3 = hval(a.w);
        float h4 = hval(b2.x), h5 = hval(b2.y), h6 = hval(b2.z), h7 = hval(b2.w);
        s = __fadd_rn(s, h0); s = __fadd_rn(s, h1);
        s = __fadd_rn(s, h2); s = __fadd_rn(s, h3);
        s = __fadd_rn(s, h4); s = __fadd_rn(s, h5);
        s = __fadd_rn(s, h6); s = __fadd_rn(s, h7);
    }
    #pragma unroll 1
    for (; i < dc; i++)
        s = __fadd_rn(s, hval(bk[i]));
    float dg = fmaxf((float)d, 1.0f);
    float ni = __fdiv_rn(1.0f, __fsqrt_rn(dg));
    float score = __fadd_rn(__fmul_rn(s, ni), b[0]);
    g_scoref[v] = score;

    // softmax denominator partial
    dred[tid] = (double)expf(score);
    __syncthreads();
    for (int o = 128; o; o >>= 1) {
        if (tid < o) dred[tid] += dred[tid + o];
        __syncthreads();
    }
    if (tid == 0) atomicAdd(g_sum, dred[0]);
}

// per-graph top-k via rank counting (64-bit monotonic keys, low-idx ties),
// complement via warp-ballot popc prefix. One block (416 thr) per graph.
#define TPK_T 416
__global__ __launch_bounds__(TPK_T) void k_topk(float* __restrict__ out) {
    __shared__ unsigned long long key[NND];
    __shared__ short rnk[NND];
    __shared__ unsigned int nsmask[TPK_T / 32];
    int g = blockIdx.x;
    int t = threadIdx.x;

    if (t < NND) {
        float v = g_scoref[g * NND + t];
        unsigned int bb = __float_as_uint(v);
        unsigned int mp = (bb & 0x80000000u) ? ~bb : (bb | 0x80000000u);
        // higher key = better; tie -> lower index wins (bigger low field)
        key[t] = ((unsigned long long)mp << 16) | (unsigned int)(1023 - t);
    }
    __syncthreads();

    if (t < NND) {
        unsigned long long mine = key[t];
        int r = 0;
        #pragma unroll 4
        for (int i = 0; i < NND; i++)
            r += (key[i] > mine) ? 1 : 0;
        rnk[t] = (short)r;
        int node = g * NND + t;
        if (r < KSEL) {
            g_permi[g * KSEL + r] = node;
            g_sel[node] = 1;
            out[O_PERM + (size_t)g * KSEL + r] = (float)node;
        } else {
            g_sel[node] = 0;
        }
    }
    __syncthreads();

    {
        int w = t >> 5, lane = t & 31;
        bool notsel = (t < NND) && (rnk[t] >= KSEL);
        unsigned m = __ballot_sync(0xffffffffu, notsel);
        if (lane == 0) nsmask[w] = m;
    }
    __syncthreads();

    if (t < NND && rnk[t] >= KSEL) {
        int w = t >> 5, lane = t & 31;
        int cr = __popc(nsmask[w] & ((1u << lane) - 1u));
        #pragma unroll
        for (int j = 0; j < TPK_T / 32; j++)
            cr += (j < w) ? __popc(nsmask[j]) : 0;
        int node = g * NND + t;
        g_comi[g * NCOM + cr] = node;
        out[O_PCOM + (size_t)g * NCOM + cr] = (float)node;
    }
}

// fused epilogue: gather [0,25600), mask [25600,38400), soft [38400,38800)
__global__ __launch_bounds__(256) void k_epi(const float* __restrict__ f,
                                             const int* __restrict__ src,
                                             const int* __restrict__ dst,
                                             float* __restrict__ out) {
    int b   = blockIdx.x;
    int tid = threadIdx.x;

    if (b < EP_GATHER) {
        long long id  = (long long)b * 256 + tid;
        long long row = id >> 6;
        int       u   = (int)(id & 63);
        int       node;
        size_t    base;
        long long r;
        if (row < BK) { node = g_permi[row];     base = O_FDIS; r = row; }
        else          { node = g_comi[row - BK]; base = O_FCOM; r = row - BK; }
        float s = tanhf(g_scoref[node]);
        const float4* fr = reinterpret_cast<const float4*>(f) + (size_t)node * (DIM / 4);
        float4 v = fr[u];
        v.x = __fmul_rn(v.x, s); v.y = __fmul_rn(v.y, s);
        v.z = __fmul_rn(v.z, s); v.w = __fmul_rn(v.w, s);
        reinterpret_cast<float4*>(out + base)[(size_t)r * (DIM / 4) + u] = v;
    } else if (b < EP_GATHER + EP_MASK) {
        int e = (b - EP_GATHER) * 256 + tid;
        int a  = g_sel[src[e]];
        int b2 = g_sel[dst[e]];
        out[O_EDIS + e] = (a & b2)        ? 1.0f : 0.0f;
        out[O_ECOM + e] = ((a | b2) == 0) ? 1.0f : 0.0f;
    } else {
        int v = (b - EP_GATHER - EP_MASK) * 256 + tid;
        float sumf = (float)g_sum[0];
        float ex   = expf(g_scoref[v]);
        out[O_SOFT + v] = __fdiv_rn(ex, sumf);
    }
}

// ---------------- launch --------------------------------------------------
extern "C" void kernel_launch(void* const* d_in, const int* in_sizes, int n_in,
                              void* d_out, int out_size) {
    const float* feature = (const float*)d_in[0];
    const float* W       = (const float*)d_in[1];
    const float* b       = (const float*)d_in[2];
    const int*   src     = (const int*)d_in[3];
    const int*   dst     = (const int*)d_in[4];
    float*       out     = (float*)d_out;

    kA<<<A_GRID, 1024>>>(src, dst, feature, W);
    k_agg<<<NTOT / 256, 256>>>(b);
    k_topk<<<BGR, TPK_T>>>(out);
    k_epi<<<EP_GRID, 256>>>(feature, src, dst, out);
}

// round 15
// speedup vs baseline: 3.4087x; 1.1079x over previous
#include <cuda_runtime.h>
#include <cuda_bf16.h>
#include <float.h>
#include <math.h>

// ---------------- problem constants ----------------
#define BGR   256
#define NND   400
#define DIM   256
#define DEG   32
#define EDG   (BGR * NND * DEG)   // 3,276,800
#define KSEL  200
#define NCOM  (NND - KSEL)        // 200
#define NTOT  (BGR * NND)         // 102,400
#define BK    (BGR * KSEL)        // 51,200
#define BC    (BGR * NCOM)        // 51,200
#define STRIDE 96
#define EPG   (NND * DEG)         // 12,800 edges/graph
#define BWRP  32
#define EPW   (EPG / BWRP)        // 400 edges/warp

// fused kernel A grid split
#define XW_BLOCKS  (NTOT / 32)    // 3200
#define A_GRID     (BGR + XW_BLOCKS)

// epilogue grid split (256 threads/block)
#define EP_G2   ((2 * BK) / 8)         // 12800 gather blocks (8 rows/block, warp/row)
#define EP_M2   (EDG / 1024)           // 3200 mask blocks (4 edges/thread)
#define EP_S    (NTOT / 256)           // 400 softmax blocks
#define EP_GRID (EP_G2 + EP_M2 + EP_S)

// output layout (float32 concatenation)
#define O_FDIS  ((size_t)0)
#define O_FCOM  (O_FDIS + (size_t)BK * DIM)
#define O_PERM  (O_FCOM + (size_t)BC * DIM)
#define O_PCOM  (O_PERM + (size_t)BK)
#define O_SOFT  (O_PCOM + (size_t)BC)
#define O_EDIS  (O_SOFT + (size_t)NTOT)
#define O_ECOM  (O_EDIS + (size_t)EDG)

// ---------------- device-global scratch ----------------
__device__ float          g_dot[NTOT];    // raw feature.W
__device__ float          g_h[NTOT];      // dot * norm_out
__device__ float          g_scoref[NTOT];
__device__ int            g_degout[NTOT];
__device__ int            g_degin[NTOT];
__device__ unsigned char  g_sel[NTOT];
__device__ int2           g_pdis[BK];     // {node, tanh(score) bits} per selected row
__device__ int2           g_pcom[BC];     // same for complement rows
__device__ double         g_sum[1];       // softmax denominator
__device__ int            g_bucket[(size_t)NTOT * STRIDE]; // in-edges, EDGE-ID ORDER

// ---------------- fused kernel A: bucket build (blocks<BGR) + X.W dot ------
__global__ __launch_bounds__(1024) void kA(const int* __restrict__ src,
                                           const int* __restrict__ dst,
                                           const float* __restrict__ f,
                                           const float* __restrict__ W) {
    int tid  = threadIdx.x;
    int w    = tid >> 5;
    int lane = tid & 31;

    if (blockIdx.x >= BGR) {
        // ---- X.W raw dot: warp per node ----
        int node = (blockIdx.x - BGR) * 32 + w;
        const float4* fr = reinterpret_cast<const float4*>(f) + (size_t)node * (DIM / 4);
        const float4* w4 = reinterpret_cast<const float4*>(W);
        float s = 0.0f;
        #pragma unroll
        for (int half = 0; half < 2; half++) {
            float4 a = fr[lane + half * 32];
            float4 wv = w4[lane + half * 32];
            s = fmaf(a.x, wv.x, s);
            s = fmaf(a.y, wv.y, s);
            s = fmaf(a.z, wv.z, s);
            s = fmaf(a.w, wv.w, s);
        }
        #pragma unroll
        for (int o = 16; o; o >>= 1)
            s = __fadd_rn(s, __shfl_down_sync(0xffffffffu, s, o));
        if (lane == 0) g_dot[node] = s;
        return;
    }

    // ---- deterministic bucket build: one block per graph ----
    __shared__ int cnt[BWRP][NND];   // 51.2 KB
    __shared__ int cout[NND];
    int g = blockIdx.x;
    if (g == 0 && tid == 0) g_sum[0] = 0.0;

    for (int i = tid; i < BWRP * NND; i += 1024) (&cnt[0][0])[i] = 0;
    for (int i = tid; i < NND; i += 1024) cout[i] = 0;
    __syncthreads();

    int wbase = g * EPG + w * EPW;

    // Phase 1: counts (order-free)
    #pragma unroll 1
    for (int it = 0; it < (EPW + 31) / 32; it++) {
        int li = it * 32 + lane;
        if (li < EPW) {
            int e = wbase + li;
            atomicAdd(&cnt[w][dst[e] - g * NND], 1);
            atomicAdd(&cout[src[e] - g * NND], 1);
        }
    }
    __syncthreads();

    // Phase 2: exclusive scan across warps per dst
    for (int d = tid; d < NND; d += 1024) {
        int run = 0;
        #pragma unroll
        for (int w2 = 0; w2 < BWRP; w2++) {
            int c = cnt[w2][d];
            cnt[w2][d] = run;
            run += c;
        }
        g_degin[g * NND + d]  = run;
        g_degout[g * NND + d] = cout[d];
    }
    __syncthreads();

    // Phase 3: ordered replay (slots == sequential edge-order scatter)
    #pragma unroll 1
    for (int it = 0; it < (EPW + 31) / 32; it++) {
        int li = it * 32 + lane;
        bool act = (li < EPW);
        int s = 0, d = 0, key;
        if (act) {
            int e = wbase + li;
            s = src[e];
            d = dst[e];
            key = d - g * NND;
        } else {
            key = NND + lane;
        }
        unsigned m    = __match_any_sync(0xffffffffu, key);
        int      lead = __ffs(m) - 1;
        int      rank = __popc(m & ((1u << lane) - 1u));
        int cb = 0;
        if (act) cb = cnt[w][key];
        __syncwarp();
        if (act) {
            int slot = cb + rank;
            if (slot < STRIDE)
                g_bucket[(size_t)d * STRIDE + slot] = s;
            if (lane == lead)
                cnt[w][key] = cb + __popc(m);
        }
        __syncwarp();
    }
}

// h[v] = dot[v] * norm_out[v]  (tiny stream pass; same rounding as always)
__global__ void k_norm() {
    int v = blockIdx.x * blockDim.x + threadIdx.x;
    if (v < NTOT) {
        float dg = fmaxf((float)g_degout[v], 1.0f);
        float no = __fdiv_rn(1.0f, __fsqrt_rn(dg));
        g_h[v] = __fmul_rn(g_dot[v], no);
    }
}

// agg[v] = sequential fp32 sum over in-edges IN EDGE ORDER; score = agg*ni + b.
// Also accumulates the softmax denominator (fp64, one atomic per block).
__global__ __launch_bounds__(256) void k_agg(const float* __restrict__ b) {
    __shared__ double dred[256];
    int tid = threadIdx.x;
    int v = blockIdx.x * 256 + tid;

    int d  = g_degin[v];
    int dc = d < STRIDE ? d : STRIDE;
    const int* bk = g_bucket + (size_t)v * STRIDE;
    float s = 0.0f;
    int i = 0;
    #pragma unroll 1
    for (; i + 8 <= dc; i += 8) {
        int4 a  = *reinterpret_cast<const int4*>(bk + i);
        int4 b2 = *reinterpret_cast<const int4*>(bk + i + 4);
        float h0 = g_h[a.x],  h1 = g_h[a.y],  h2 = g_h[a.z],  h3 = g_h[a.w];
        float h4 = g_h[b2.x], h5 = g_h[b2.y], h6 = g_h[b2.z], h7 = g_h[b2.w];
        s = __fadd_rn(s, h0); s = __fadd_rn(s, h1);
        s = __fadd_rn(s, h2); s = __fadd_rn(s, h3);
        s = __fadd_rn(s, h4); s = __fadd_rn(s, h5);
        s = __fadd_rn(s, h6); s = __fadd_rn(s, h7);
    }
    #pragma unroll 1
    for (; i < dc; i++)
        s = __fadd_rn(s, g_h[bk[i]]);
    float dg = fmaxf((float)d, 1.0f);
    float ni = __fdiv_rn(1.0f, __fsqrt_rn(dg));
    float score = __fadd_rn(__fmul_rn(s, ni), b[0]);
    g_scoref[v] = score;

    // softmax denominator partial
    dred[tid] = (double)expf(score);
    __syncthreads();
    for (int o = 128; o; o >>= 1) {
        if (tid < o) dred[tid] += dred[tid + o];
        __syncthreads();
    }
    if (tid == 0) atomicAdd(g_sum, dred[0]);
}

// per-graph top-k via rank counting (64-bit monotonic keys, low-idx ties),
// complement via warp-ballot popc prefix. Emits packed {node, tanh} rows.
#define TPK_T 416
__global__ __launch_bounds__(TPK_T) void k_topk(float* __restrict__ out) {
    __shared__ unsigned long long key[NND];
    __shared__ float sc[NND];
    __shared__ short rnk[NND];
    __shared__ unsigned int nsmask[TPK_T / 32];
    int g = blockIdx.x;
    int t = threadIdx.x;

    if (t < NND) {
        float v = g_scoref[g * NND + t];
        sc[t] = v;
        unsigned int bb = __float_as_uint(v);
        unsigned int mp = (bb & 0x80000000u) ? ~bb : (bb | 0x80000000u);
        // higher key = better; tie -> lower index wins (bigger low field)
        key[t] = ((unsigned long long)mp << 16) | (unsigned int)(1023 - t);
    }
    __syncthreads();

    if (t < NND) {
        unsigned long long mine = key[t];
        int r = 0;
        #pragma unroll 4
        for (int i = 0; i < NND; i++)
            r += (key[i] > mine) ? 1 : 0;
        rnk[t] = (short)r;
        int node = g * NND + t;
        if (r < KSEL) {
            float th = tanhf(sc[t]);
            g_pdis[g * KSEL + r] = make_int2(node, __float_as_int(th));
            g_sel[node] = 1;
            out[O_PERM + (size_t)g * KSEL + r] = (float)node;
        } else {
            g_sel[node] = 0;
        }
    }
    __syncthreads();

    {
        int w = t >> 5, lane = t & 31;
        bool notsel = (t < NND) && (rnk[t] >= KSEL);
        unsigned m = __ballot_sync(0xffffffffu, notsel);
        if (lane == 0) nsmask[w] = m;
    }
    __syncthreads();

    if (t < NND && rnk[t] >= KSEL) {
        int w = t >> 5, lane = t & 31;
        int cr = __popc(nsmask[w] & ((1u << lane) - 1u));
        #pragma unroll
        for (int j = 0; j < TPK_T / 32; j++)
            cr += (j < w) ? __popc(nsmask[j]) : 0;
        int node = g * NND + t;
        float th = tanhf(sc[t]);
        g_pcom[g * NCOM + cr] = make_int2(node, __float_as_int(th));
        out[O_PCOM + (size_t)g * NCOM + cr] = (float)node;
    }
}

// fused epilogue:
//  gather blocks [0, EP_G2): warp per row, 2 float4/thread (MLP=2)
//  mask   blocks [EP_G2, EP_G2+EP_M2): 4 edges/thread, float4 stores
//  soft   blocks rest
__global__ __launch_bounds__(256) void k_epi(const float* __restrict__ f,
                                             const int* __restrict__ src,
                                             const int* __restrict__ dst,
                                             float* __restrict__ out) {
    int b   = blockIdx.x;
    int tid = threadIdx.x;

    if (b < EP_G2) {
        int w = tid >> 5;
        int u = tid & 31;
        long long row = (long long)b * 8 + w;
        int2 p;
        size_t base;
        long long r;
        if (row < BK) { p = g_pdis[row];      base = O_FDIS; r = row; }
        else          { p = g_pcom[row - BK]; base = O_FCOM; r = row - BK; }
        float s = __int_as_float(p.y);
        const float4* fr = reinterpret_cast<const float4*>(f) + (size_t)p.x * (DIM / 4);
        float4 v0 = fr[u];
        float4 v1 = fr[u + 32];
        v0.x = __fmul_rn(v0.x, s); v0.y = __fmul_rn(v0.y, s);
        v0.z = __fmul_rn(v0.z, s); v0.w = __fmul_rn(v0.w, s);
        v1.x = __fmul_rn(v1.x, s); v1.y = __fmul_rn(v1.y, s);
        v1.z = __fmul_rn(v1.z, s); v1.w = __fmul_rn(v1.w, s);
        float4* orow = reinterpret_cast<float4*>(out + base) + (size_t)r * (DIM / 4);
        orow[u]      = v0;
        orow[u + 32] = v1;
    } else if (b < EP_G2 + EP_M2) {
        int e = (b - EP_G2) * 1024 + tid * 4;
        int4 s4 = *reinterpret_cast<const int4*>(src + e);
        int4 d4 = *reinterpret_cast<const int4*>(dst + e);
        int a0 = g_sel[s4.x], a1 = g_sel[s4.y], a2 = g_sel[s4.z], a3 = g_sel[s4.w];
        int b0 = g_sel[d4.x], b1 = g_sel[d4.y], b2 = g_sel[d4.z], b3 = g_sel[d4.w];
        float4 dis = make_float4((a0 & b0) ? 1.0f : 0.0f, (a1 & b1) ? 1.0f : 0.0f,
                                 (a2 & b2) ? 1.0f : 0.0f, (a3 & b3) ? 1.0f : 0.0f);
        float4 com = make_float4(((a0 | b0) == 0) ? 1.0f : 0.0f, ((a1 | b1) == 0) ? 1.0f : 0.0f,
                                 ((a2 | b2) == 0) ? 1.0f : 0.0f, ((a3 | b3) == 0) ? 1.0f : 0.0f);
        *reinterpret_cast<float4*>(out + O_EDIS + e) = dis;
        *reinterpret_cast<float4*>(out + O_ECOM + e) = com;
    } else {
        int v = (b - EP_G2 - EP_M2) * 256 + tid;
        float sumf = (float)g_sum[0];
        float ex   = expf(g_scoref[v]);
        out[O_SOFT + v] = __fdiv_rn(ex, sumf);
    }
}

// ---------------- launch --------------------------------------------------
extern "C" void kernel_launch(void* const* d_in, const int* in_sizes, int n_in,
                              void* d_out, int out_size) {
    const float* feature = (const float*)d_in[0];
    const float* W       = (const float*)d_in[1];
    const float* b       = (const float*)d_in[2];
    const int*   src     = (const int*)d_in[3];
    const int*   dst     = (const int*)d_in[4];
    float*       out     = (float*)d_out;

    kA<<<A_GRID, 1024>>>(src, dst, feature, W);
    k_norm<<<NTOT / 256, 256>>>();
    k_agg<<<NTOT / 256, 256>>>(b);
    k_topk<<<BGR, TPK_T>>>(out);
    k_epi<<<EP_GRID, 256>>>(feature, src, dst, out);
}

// round 16
// speedup vs baseline: 3.5249x; 1.0341x over previous
#include <cuda_runtime.h>
#include <cuda_bf16.h>
#include <float.h>
#include <math.h>

// ---------------- problem constants ----------------
#define BGR   256
#define NND   400
#define DIM   256
#define DEG   32
#define EDG   (BGR * NND * DEG)   // 3,276,800
#define KSEL  200
#define NCOM  (NND - KSEL)        // 200
#define NTOT  (BGR * NND)         // 102,400
#define BK    (BGR * KSEL)        // 51,200
#define BC    (BGR * NCOM)        // 51,200
#define STRIDE 96
#define EPG   (NND * DEG)         // 12,800 edges/graph
#define BWRP  32
#define EPW   (EPG / BWRP)        // 400 edges/warp

// fused kernel A grid split
#define XW_BLOCKS  (NTOT / 32)    // 3200
#define A_GRID     (BGR + XW_BLOCKS)

// epilogue grid split (256 threads/block)
#define EP_G2   ((2 * BK) / 8)         // 12800 gather blocks (8 rows/block, warp/row)
#define EP_M2   (EDG / 1024)           // 3200 mask blocks (4 edges/thread)
#define EP_S    (NTOT / 256)           // 400 softmax blocks
#define EP_GRID (EP_G2 + EP_M2 + EP_S)

// output layout (float32 concatenation)
#define O_FDIS  ((size_t)0)
#define O_FCOM  (O_FDIS + (size_t)BK * DIM)
#define O_PERM  (O_FCOM + (size_t)BC * DIM)
#define O_PCOM  (O_PERM + (size_t)BK)
#define O_SOFT  (O_PCOM + (size_t)BC)
#define O_EDIS  (O_SOFT + (size_t)NTOT)
#define O_ECOM  (O_EDIS + (size_t)EDG)

// ---------------- device-global scratch ----------------
__device__ float          g_dot[NTOT];    // raw feature.W
__device__ float          g_h[NTOT];      // dot * norm_out
__device__ float          g_scoref[NTOT];
__device__ int            g_degout[NTOT];
__device__ int            g_degin[NTOT];
__device__ unsigned char  g_sel[NTOT];
__device__ int2           g_pdis[BK];     // {node, tanh(score) bits}
__device__ int2           g_pcom[BC];
__device__ double         g_sum[1];       // softmax denominator
__device__ int            g_bucket[(size_t)NTOT * STRIDE]; // in-edges, EDGE-ID ORDER

// ---------------- fused kernel A: bucket build (blocks<BGR) + X.W dot ------
__global__ __launch_bounds__(1024) void kA(const int* __restrict__ src,
                                           const int* __restrict__ dst,
                                           const float* __restrict__ f,
                                           const float* __restrict__ W) {
    int tid  = threadIdx.x;
    int w    = tid >> 5;
    int lane = tid & 31;

    if (blockIdx.x >= BGR) {
        // ---- X.W raw dot: warp per node ----
        int node = (blockIdx.x - BGR) * 32 + w;
        const float4* fr = reinterpret_cast<const float4*>(f) + (size_t)node * (DIM / 4);
        const float4* w4 = reinterpret_cast<const float4*>(W);
        float s = 0.0f;
        #pragma unroll
        for (int half = 0; half < 2; half++) {
            float4 a = fr[lane + half * 32];
            float4 wv = w4[lane + half * 32];
            s = fmaf(a.x, wv.x, s);
            s = fmaf(a.y, wv.y, s);
            s = fmaf(a.z, wv.z, s);
            s = fmaf(a.w, wv.w, s);
        }
        #pragma unroll
        for (int o = 16; o; o >>= 1)
            s = __fadd_rn(s, __shfl_down_sync(0xffffffffu, s, o));
        if (lane == 0) g_dot[node] = s;
        return;
    }

    // ---- deterministic bucket build: one block per graph ----
    __shared__ int cnt[BWRP][NND];   // 51.2 KB
    __shared__ int cout[NND];
    int g = blockIdx.x;
    if (g == 0 && tid == 0) g_sum[0] = 0.0;

    for (int i = tid; i < BWRP * NND; i += 1024) (&cnt[0][0])[i] = 0;
    for (int i = tid; i < NND; i += 1024) cout[i] = 0;
    __syncthreads();

    int wbase = g * EPG + w * EPW;

    // Phase 1: counts (order-free)
    #pragma unroll 1
    for (int it = 0; it < (EPW + 31) / 32; it++) {
        int li = it * 32 + lane;
        if (li < EPW) {
            int e = wbase + li;
            atomicAdd(&cnt[w][dst[e] - g * NND], 1);
            atomicAdd(&cout[src[e] - g * NND], 1);
        }
    }
    __syncthreads();

    // Phase 2: exclusive scan across warps per dst
    for (int d = tid; d < NND; d += 1024) {
        int run = 0;
        #pragma unroll
        for (int w2 = 0; w2 < BWRP; w2++) {
            int c = cnt[w2][d];
            cnt[w2][d] = run;
            run += c;
        }
        g_degin[g * NND + d]  = run;
        g_degout[g * NND + d] = cout[d];
    }
    __syncthreads();

    // Phase 3: ordered replay (slots == sequential edge-order scatter)
    #pragma unroll 1
    for (int it = 0; it < (EPW + 31) / 32; it++) {
        int li = it * 32 + lane;
        bool act = (li < EPW);
        int s = 0, d = 0, key;
        if (act) {
            int e = wbase + li;
            s = src[e];
            d = dst[e];
            key = d - g * NND;
        } else {
            key = NND + lane;
        }
        unsigned m    = __match_any_sync(0xffffffffu, key);
        int      lead = __ffs(m) - 1;
        int      rank = __popc(m & ((1u << lane) - 1u));
        int cb = 0;
        if (act) cb = cnt[w][key];
        __syncwarp();
        if (act) {
            int slot = cb + rank;
            if (slot < STRIDE)
                g_bucket[(size_t)d * STRIDE + slot] = s;
            if (lane == lead)
                cnt[w][key] = cb + __popc(m);
        }
        __syncwarp();
    }
}

// h[v] = dot[v] * norm_out[v]
__global__ void k_norm() {
    int v = blockIdx.x * blockDim.x + threadIdx.x;
    if (v < NTOT) {
        float dg = fmaxf((float)g_degout[v], 1.0f);
        float no = __fdiv_rn(1.0f, __fsqrt_rn(dg));
        g_h[v] = __fmul_rn(g_dot[v], no);
    }
}

// Fused score + top-k: one block (416 thr) per graph.
//  phase 1: per-node edge-order fp32 sum -> score (memory-bound)
//  phase 2: fp64 exp-sum block reduction (softmax denominator)
//  phase 3: rank counting over 64-bit monotonic keys (issue-bound; overlaps
//           phase 1 of co-resident blocks), emit perm/com + packed descriptors
#define TPK_T 416
#define NKEY2 (TPK_T / 2)   // 208 ulonglong2 = 416 keys (400 real + 16 pad)
__global__ __launch_bounds__(TPK_T) void k_score(const float* __restrict__ b,
                                                 float* __restrict__ out) {
    __shared__ ulonglong2 key2[NKEY2];
    __shared__ float  sc[NND];
    __shared__ short  rnk[NND];
    __shared__ double dred[512];
    __shared__ unsigned int nsmask[TPK_T / 32];
    unsigned long long* key = reinterpret_cast<unsigned long long*>(key2);

    int g = blockIdx.x;
    int t = threadIdx.x;

    // ---- phase 1: score for node t ----
    float score = 0.0f;
    if (t < NND) {
        int v  = g * NND + t;
        int d  = g_degin[v];
        int dc = d < STRIDE ? d : STRIDE;
        const int* bk = g_bucket + (size_t)v * STRIDE;
        float s = 0.0f;
        int i = 0;
        #pragma unroll 1
        for (; i + 8 <= dc; i += 8) {
            int4 a  = *reinterpret_cast<const int4*>(bk + i);
            int4 b2 = *reinterpret_cast<const int4*>(bk + i + 4);
            float h0 = g_h[a.x],  h1 = g_h[a.y],  h2 = g_h[a.z],  h3 = g_h[a.w];
            float h4 = g_h[b2.x], h5 = g_h[b2.y], h6 = g_h[b2.z], h7 = g_h[b2.w];
            s = __fadd_rn(s, h0); s = __fadd_rn(s, h1);
            s = __fadd_rn(s, h2); s = __fadd_rn(s, h3);
            s = __fadd_rn(s, h4); s = __fadd_rn(s, h5);
            s = __fadd_rn(s, h6); s = __fadd_rn(s, h7);
        }
        #pragma unroll 1
        for (; i < dc; i++)
            s = __fadd_rn(s, g_h[bk[i]]);
        float dg = fmaxf((float)d, 1.0f);
        float ni = __fdiv_rn(1.0f, __fsqrt_rn(dg));
        score = __fadd_rn(__fmul_rn(s, ni), b[0]);
        g_scoref[v] = score;
        sc[t] = score;
        unsigned int bb = __float_as_uint(score);
        unsigned int mp = (bb & 0x80000000u) ? ~bb : (bb | 0x80000000u);
        key[t] = ((unsigned long long)mp << 16) | (unsigned int)(1023 - t);
    } else {
        key[t] = 0ull;   // pad: smaller than any real key
    }

    // ---- phase 2: softmax denominator partial ----
    dred[t] = (t < NND) ? (double)expf(score) : 0.0;
    if (t < 512 - TPK_T) dred[TPK_T + t] = 0.0;
    __syncthreads();
    for (int o = 256; o; o >>= 1) {
        if (t < o) dred[t] += dred[t + o];
        __syncthreads();
    }
    if (t == 0) atomicAdd(g_sum, dred[0]);

    // ---- phase 3: rank counting (2 keys per LDS.128) ----
    if (t < NND) {
        unsigned long long mine = key[t];
        int r = 0;
        #pragma unroll 4
        for (int i = 0; i < NKEY2; i++) {
            ulonglong2 kk = key2[i];
            r += (kk.x > mine) ? 1 : 0;
            r += (kk.y > mine) ? 1 : 0;
        }
        rnk[t] = (short)r;
        int node = g * NND + t;
        if (r < KSEL) {
            float th = tanhf(sc[t]);
            g_pdis[g * KSEL + r] = make_int2(node, __float_as_int(th));
            g_sel[node] = 1;
            out[O_PERM + (size_t)g * KSEL + r] = (float)node;
        } else {
            g_sel[node] = 0;
        }
    }
    __syncthreads();

    {
        int w = t >> 5, lane = t & 31;
        bool notsel = (t < NND) && (rnk[t] >= KSEL);
        unsigned m = __ballot_sync(0xffffffffu, notsel);
        if (lane == 0) nsmask[w] = m;
    }
    __syncthreads();

    if (t < NND && rnk[t] >= KSEL) {
        int w = t >> 5, lane = t & 31;
        int cr = __popc(nsmask[w] & ((1u << lane) - 1u));
        #pragma unroll
        for (int j = 0; j < TPK_T / 32; j++)
            cr += (j < w) ? __popc(nsmask[j]) : 0;
        int node = g * NND + t;
        float th = tanhf(sc[t]);
        g_pcom[g * NCOM + cr] = make_int2(node, __float_as_int(th));
        out[O_PCOM + (size_t)g * NCOM + cr] = (float)node;
    }
}

// fused epilogue:
//  gather blocks [0, EP_G2): warp per row, 2 float4/thread (MLP=2)
//  mask   blocks [EP_G2, EP_G2+EP_M2): 4 edges/thread, float4 stores
//  soft   blocks rest
__global__ __launch_bounds__(256) void k_epi(const float* __restrict__ f,
                                             const int* __restrict__ src,
                                             const int* __restrict__ dst,
                                             float* __restrict__ out) {
    int b   = blockIdx.x;
    int tid = threadIdx.x;

    if (b < EP_G2) {
        int w = tid >> 5;
        int u = tid & 31;
        long long row = (long long)b * 8 + w;
        int2 p;
        size_t base;
        long long r;
        if (row < BK) { p = g_pdis[row];      base = O_FDIS; r = row; }
        else          { p = g_pcom[row - BK]; base = O_FCOM; r = row - BK; }
        float s = __int_as_float(p.y);
        const float4* fr = reinterpret_cast<const float4*>(f) + (size_t)p.x * (DIM / 4);
        float4 v0 = fr[u];
        float4 v1 = fr[u + 32];
        v0.x = __fmul_rn(v0.x, s); v0.y = __fmul_rn(v0.y, s);
        v0.z = __fmul_rn(v0.z, s); v0.w = __fmul_rn(v0.w, s);
        v1.x = __fmul_rn(v1.x, s); v1.y = __fmul_rn(v1.y, s);
        v1.z = __fmul_rn(v1.z, s); v1.w = __fmul_rn(v1.w, s);
        float4* orow = reinterpret_cast<float4*>(out + base) + (size_t)r * (DIM / 4);
        orow[u]      = v0;
        orow[u + 32] = v1;
    } else if (b < EP_G2 + EP_M2) {
        int e = (b - EP_G2) * 1024 + tid * 4;
        int4 s4 = *reinterpret_cast<const int4*>(src + e);
        int4 d4 = *reinterpret_cast<const int4*>(dst + e);
        int a0 = g_sel[s4.x], a1 = g_sel[s4.y], a2 = g_sel[s4.z], a3 = g_sel[s4.w];
        int b0 = g_sel[d4.x], b1 = g_sel[d4.y], b2 = g_sel[d4.z], b3 = g_sel[d4.w];
        float4 dis = make_float4((a0 & b0) ? 1.0f : 0.0f, (a1 & b1) ? 1.0f : 0.0f,
                                 (a2 & b2) ? 1.0f : 0.0f, (a3 & b3) ? 1.0f : 0.0f);
        float4 com = make_float4(((a0 | b0) == 0) ? 1.0f : 0.0f, ((a1 | b1) == 0) ? 1.0f : 0.0f,
                                 ((a2 | b2) == 0) ? 1.0f : 0.0f, ((a3 | b3) == 0) ? 1.0f : 0.0f);
        *reinterpret_cast<float4*>(out + O_EDIS + e) = dis;
        *reinterpret_cast<float4*>(out + O_ECOM + e) = com;
    } else {
        int v = (b - EP_G2 - EP_M2) * 256 + tid;
        float sumf = (float)g_sum[0];
        float ex   = expf(g_scoref[v]);
        out[O_SOFT + v] = __fdiv_rn(ex, sumf);
    }
}

// ---------------- launch --------------------------------------------------
extern "C" void kernel_launch(void* const* d_in, const int* in_sizes, int n_in,
                              void* d_out, int out_size) {
    const float* feature = (const float*)d_in[0];
    const float* W       = (const float*)d_in[1];
    const float* b       = (const float*)d_in[2];
    const int*   src     = (const int*)d_in[3];
    const int*   dst     = (const int*)d_in[4];
    float*       out     = (float*)d_out;

    kA<<<A_GRID, 1024>>>(src, dst, feature, W);
    k_norm<<<NTOT / 256, 256>>>();
    k_score<<<BGR, TPK_T>>>(b, out);
    k_epi<<<EP_GRID, 256>>>(feature, src, dst, out);
}